// round 1
// baseline (speedup 1.0000x reference)
#include <cuda_runtime.h>
#include <cuda_bf16.h>

// One thread = one 2x2 patch = one 4-qubit (16-amplitude) circuit, fully in registers.
//
// Circuit algebra:
//   H⊗4 then all RZ / CNOT-RZ-CNOT blocks are diagonal -> state after encoding is
//   a(b) = 0.25 * exp(i * Psi(b)),  Psi(b) = sum_q h_q*s_q(b) + sum_{i<j} h_ij*t_ij(b)
//   with s_q = +1 if bit_q(b)==1 else -1,  t_ij = +1 if bit_i^bit_j else -1,
//   h_q = x_q*0.785/2, h_ij = x_i*x_j*0.785/2.
//   (RZ(th) multiplies |0> amp by e^{-i th/2}, |1> by e^{+i th/2}; the CNOT pair
//    turns the middle RZ into a parity phase on bits i^j.)
// Then 4 RX butterflies, a CNOT ring (register permutation), probabilities, Z sums.

__global__ void __launch_bounds__(256)
qconv_kernel(const float* __restrict__ img,
             const float* __restrict__ wts,
             float* __restrict__ out,
             int npatch)
{
    int tid = blockIdx.x * blockDim.x + threadIdx.x;
    if (tid >= npatch) return;

    int b   = tid / 196;            // image index
    int rem = tid - b * 196;        // j*14 + k
    int j   = rem / 14;
    int k   = rem - j * 14;

    const float* p = img + (size_t)b * 784 + (size_t)(2 * j) * 28 + (size_t)(2 * k);
    float x0 = p[0];
    float x1 = p[1];
    float x2 = p[28];
    float x3 = p[29];

    const float HR = 0.785f * 0.5f;
    float h0 = x0 * HR, h1 = x1 * HR, h2 = x2 * HR, h3 = x3 * HR;
    // pairs (0,1)(0,2)(0,3)(1,2)(1,3)(2,3)
    float p01 = x0 * x1 * HR;
    float p02 = x0 * x2 * HR;
    float p03 = x0 * x3 * HR;
    float p12 = x1 * x2 * HR;
    float p13 = x1 * x3 * HR;
    float p23 = x2 * x3 * HR;

    // amplitude index s = b0*8 + b1*4 + b2*2 + b3  (qubit 0 = MSB, matching axis order)
    float ar[16], ai[16];
#pragma unroll
    for (int s = 0; s < 16; ++s) {
        int b0 = (s >> 3) & 1, b1 = (s >> 2) & 1, b2 = (s >> 1) & 1, b3 = s & 1;
        float psi = (b0 ? h0 : -h0) + (b1 ? h1 : -h1)
                  + (b2 ? h2 : -h2) + (b3 ? h3 : -h3);
        psi += ((b0 ^ b1) ? p01 : -p01);
        psi += ((b0 ^ b2) ? p02 : -p02);
        psi += ((b0 ^ b3) ? p03 : -p03);
        psi += ((b1 ^ b2) ? p12 : -p12);
        psi += ((b1 ^ b3) ? p13 : -p13);
        psi += ((b2 ^ b3) ? p23 : -p23);
        float sn, cs;
        __sincosf(psi, &sn, &cs);
        ar[s] = 0.25f * cs;
        ai[s] = 0.25f * sn;
    }

    // RX(w_q) on each qubit: [[c, -i s],[-i s, c]] with c=cos(w/2), s=sin(w/2)
    float w0 = wts[0], w1 = wts[1], w2 = wts[2], w3 = wts[3];
    float wv[4] = { w0, w1, w2, w3 };
#pragma unroll
    for (int q = 0; q < 4; ++q) {
        float sw, cw;
        __sincosf(wv[q] * 0.5f, &sw, &cw);
        int bit = 1 << (3 - q);
#pragma unroll
        for (int s = 0; s < 16; ++s) {
            if (s & bit) continue;
            int t = s | bit;
            float a0r = ar[s], a0i = ai[s];
            float a1r = ar[t], a1i = ai[t];
            ar[s] = cw * a0r + sw * a1i;
            ai[s] = cw * a0i - sw * a1r;
            ar[t] = cw * a1r + sw * a0i;
            ai[t] = cw * a1i - sw * a0r;
        }
    }

    // CNOT ring: (0,1),(1,2),(2,3),(3,0). Pure amplitude permutation (free in regs).
    auto cnot = [&](int cbit, int tbit) {
#pragma unroll
        for (int s = 0; s < 16; ++s) {
            if ((s & cbit) && !(s & tbit)) {
                int t = s | tbit;
                float tr = ar[s]; ar[s] = ar[t]; ar[t] = tr;
                float ti = ai[s]; ai[s] = ai[t]; ai[t] = ti;
            }
        }
    };
    cnot(8, 4);  // CNOT(0,1)
    cnot(4, 2);  // CNOT(1,2)
    cnot(2, 1);  // CNOT(2,3)
    cnot(1, 8);  // CNOT(3,0)

    // probabilities and Z expectations
    float pz[16];
#pragma unroll
    for (int s = 0; s < 16; ++s)
        pz[s] = ar[s] * ar[s] + ai[s] * ai[s];

    float ez[4];
#pragma unroll
    for (int q = 0; q < 4; ++q) {
        int bit = 1 << (3 - q);
        float e = 0.0f;
#pragma unroll
        for (int s = 0; s < 16; ++s)
            e += (s & bit) ? -pz[s] : pz[s];
        ez[q] = e;
    }

    // output (B,4,14,14), channel order [Z3, Z2, Z1, Z0]
    float* o = out + (size_t)b * 784 + rem;
    o[0]   = ez[3];
    o[196] = ez[2];
    o[392] = ez[1];
    o[588] = ez[0];
}

extern "C" void kernel_launch(void* const* d_in, const int* in_sizes, int n_in,
                              void* d_out, int out_size) {
    const float* img = (const float*)d_in[0];
    const float* wts = (const float*)d_in[1];
    float* out = (float*)d_out;

    int B = in_sizes[0] / 784;      // 28*28 per image
    int npatch = B * 196;           // 14*14 patches per image

    int threads = 256;
    int blocks = (npatch + threads - 1) / threads;
    qconv_kernel<<<blocks, threads>>>(img, wts, out, npatch);
}

// round 2
// speedup vs baseline: 1.1083x; 1.1083x over previous
#include <cuda_runtime.h>
#include <cuda_bf16.h>

// One thread = one 2x2 patch = one 4-qubit (16-amplitude) circuit in registers.
//
// Algebra:
//  * Encoding (H layer + RZ + CNOT-RZ-CNOT blocks) is diagonal after H^4:
//      a(s) = (1/4) e^{i Psi(s)},  Psi = sum_q sgn_q h_q + sum_{i<j} sgn_ij p_ij
//    computed via an explicit shared-subexpression tree (48 FADD).
//  * RX layer: 4 register butterflies (optimal, 256 FFMA).
//  * CNOT ring is GF(2)-linear on amplitude indices -> it only permutes |a|^2.
//    Pulling the permutation into the Z-sign patterns, the 4 expectations are
//    Walsh coefficients of pz at masks {7,12,14,15}: shared partial-FWHT tree.
//  * The 1/4 amplitude scale is deferred: ez *= 1/16 at the end.

__global__ void __launch_bounds__(256)
qconv_kernel(const float* __restrict__ img,
             const float* __restrict__ wts,
             float* __restrict__ out,
             int npatch)
{
    int tid = blockIdx.x * blockDim.x + threadIdx.x;
    if (tid >= npatch) return;

    int b   = tid / 196;
    int rem = tid - b * 196;        // j*14 + k
    int j   = rem / 14;
    int k   = rem - j * 14;

    const float* base = img + (size_t)b * 784 + (size_t)(2 * j) * 28 + (size_t)(2 * k);
    float2 r0 = *reinterpret_cast<const float2*>(base);        // x0, x1
    float2 r1 = *reinterpret_cast<const float2*>(base + 28);   // x2, x3
    float x0 = r0.x, x1 = r0.y, x2 = r1.x, x3 = r1.y;

    const float HR = 0.785f * 0.5f;
    float h0 = x0 * HR, h1 = x1 * HR, h2 = x2 * HR, h3 = x3 * HR;
    float p01 = h0 * x1, p02 = h0 * x2, p03 = h0 * x3;
    float p12 = h1 * x2, p13 = h1 * x3, p23 = h2 * x3;

    // ---- single-qubit phase bases: S(s) = +/- one of SA..SH ----
    float a01 = h0 + h1, b01 = h0 - h1;
    float a23 = h2 + h3, b23 = h2 - h3;
    float SA = a01 + a23, SB = a01 - a23;
    float SC = b01 + a23, SD = b01 - a23;
    float SE = a01 + b23, SF = a01 - b23;
    float SG = b01 + b23, SH = b01 - b23;

    // ---- pair phase bases: P depends only on g=(b0^b1,b0^b2,b0^b3) ----
    float m = p12 + p13, n = p12 - p13;
    float t_pp = p01 - m, t_mm = p01 + m;
    float t_pm = p01 - n, t_mp = p01 + n;
    float u = p02 + p03, v = p02 - p03;
    float q_pp = u - p23, q_mm = u + p23;
    float q_pm = v + p23, q_mp = v - p23;

    float P111 = t_pp + q_pp;   // g=(1,1,1)
    float P110 = t_pm + q_pm;   // g=(1,1,0)
    float P101 = t_mp - q_mp;   // g=(1,0,1)
    float P100 = t_mm - q_mm;   // g=(1,0,0)
    float P011 = q_pp - t_pp;   // g=(0,1,1)
    float P010 = q_pm - t_pm;   // g=(0,1,0)
    float Pn001 = t_mp + q_mp;  // g=(0,0,1): P = -Pn001
    float Pn000 = t_mm + q_mm;  // g=(0,0,0): P = -Pn000

    // ---- Psi(s) = S(s) + P(g(s)),  s = b0*8+b1*4+b2*2+b3 ----
    float psi[16];
    psi[0]  = -SA - Pn000;
    psi[1]  = -SE - Pn001;
    psi[2]  = -SF + P010;
    psi[3]  = -SB + P011;
    psi[4]  = -SC + P100;
    psi[5]  = -SG + P101;
    psi[6]  = -SH + P110;
    psi[7]  = -SD + P111;
    psi[8]  =  SD + P111;
    psi[9]  =  SH + P110;
    psi[10] =  SG + P101;
    psi[11] =  SC + P100;
    psi[12] =  SB + P011;
    psi[13] =  SF + P010;
    psi[14] =  SE - Pn001;
    psi[15] =  SA - Pn000;

    float ar[16], ai[16];
#pragma unroll
    for (int s = 0; s < 16; ++s)
        __sincosf(psi[s], &ai[s], &ar[s]);   // unscaled: fold 1/16 at the end

    // ---- RX(w_q) butterflies ----
#pragma unroll
    for (int q = 0; q < 4; ++q) {
        float sw, cw;
        __sincosf(__ldg(wts + q) * 0.5f, &sw, &cw);
        int bit = 1 << (3 - q);
#pragma unroll
        for (int s = 0; s < 16; ++s) {
            if (s & bit) continue;
            int t = s | bit;
            float a0r = ar[s], a0i = ai[s];
            float a1r = ar[t], a1i = ai[t];
            ar[s] = cw * a0r + sw * a1i;
            ai[s] = cw * a0i - sw * a1r;
            ar[t] = cw * a1r + sw * a0i;
            ai[t] = cw * a1i - sw * a0r;
        }
    }

    // ---- probabilities ----
    float pz[16];
#pragma unroll
    for (int s = 0; s < 16; ++s)
        pz[s] = ar[s] * ar[s] + ai[s] * ai[s];

    // ---- Walsh coefficients at masks 7 (ez0), 12 (ez1), 14 (ez2), 15 (ez3) ----
    // (CNOT ring folded into the masks; ring permutes |a|^2 only.)
    float d[8], sm[8];
#pragma unroll
    for (int i = 0; i < 8; ++i) {
        d[i]  = pz[2 * i] - pz[2 * i + 1];
        sm[i] = pz[2 * i] + pz[2 * i + 1];
    }
    float dd[4], ss[4], sd[4];
#pragma unroll
    for (int i = 0; i < 4; ++i) {
        dd[i] = d[2 * i]  - d[2 * i + 1];
        ss[i] = sm[2 * i] + sm[2 * i + 1];
        sd[i] = sm[2 * i] - sm[2 * i + 1];
    }
    float ddd0 = dd[0] - dd[1], ddd1 = dd[2] - dd[3];
    float ssd0 = ss[0] - ss[1], ssd1 = ss[2] - ss[3];
    float sdd0 = sd[0] - sd[1], sdd1 = sd[2] - sd[3];

    const float SC16 = 0.0625f;
    float ez0 = (ddd0 + ddd1) * SC16;   // mask 7
    float ez1 = (ssd0 - ssd1) * SC16;   // mask 12
    float ez2 = (sdd0 - sdd1) * SC16;   // mask 14
    float ez3 = (ddd0 - ddd1) * SC16;   // mask 15

    // output (B,4,14,14), channel order [Z3, Z2, Z1, Z0]
    float* o = out + (size_t)b * 784 + rem;
    o[0]   = ez3;
    o[196] = ez2;
    o[392] = ez1;
    o[588] = ez0;
}

extern "C" void kernel_launch(void* const* d_in, const int* in_sizes, int n_in,
                              void* d_out, int out_size) {
    const float* img = (const float*)d_in[0];
    const float* wts = (const float*)d_in[1];
    float* out = (float*)d_out;

    int B = in_sizes[0] / 784;
    int npatch = B * 196;

    int threads = 256;
    int blocks = (npatch + threads - 1) / threads;
    qconv_kernel<<<blocks, threads>>>(img, wts, out, npatch);
}

// round 3
// speedup vs baseline: 1.2645x; 1.1409x over previous
#include <cuda_runtime.h>
#include <cuda_bf16.h>

// Two horizontally-adjacent patches per thread, all arithmetic in packed f32x2
// (lane0 = patch A, lane1 = patch B). Only sincos is per-lane scalar MUFU.
//
// Circuit algebra (validated in R1/R2, rel_err ~9e-7):
//  * encoding is diagonal after H^4: a(s) = (1/4) e^{i Psi(s)}, Psi via CSE tree
//  * RX layer: 4 register butterflies
//  * CNOT ring folded into Walsh masks {7,12,14,15} on |a|^2 (partial FWHT)
//  * amplitude 1/4 scale deferred to a single 1/16 on the outputs

typedef unsigned long long u64;

__device__ __forceinline__ u64 pk2(float lo, float hi) {
    u64 r; asm("mov.b64 %0,{%1,%2};" : "=l"(r) : "f"(lo), "f"(hi)); return r;
}
__device__ __forceinline__ void unpk(u64 v, float& lo, float& hi) {
    asm("mov.b64 {%0,%1},%2;" : "=f"(lo), "=f"(hi) : "l"(v));
}
__device__ __forceinline__ u64 add2(u64 a, u64 b) {
    u64 d; asm("add.rn.f32x2 %0,%1,%2;" : "=l"(d) : "l"(a), "l"(b)); return d;
}
__device__ __forceinline__ u64 sub2(u64 a, u64 b) {
    u64 d; asm("sub.rn.f32x2 %0,%1,%2;" : "=l"(d) : "l"(a), "l"(b)); return d;
}
__device__ __forceinline__ u64 mul2(u64 a, u64 b) {
    u64 d; asm("mul.rn.f32x2 %0,%1,%2;" : "=l"(d) : "l"(a), "l"(b)); return d;
}
__device__ __forceinline__ u64 fma2(u64 a, u64 b, u64 c) {
    u64 d; asm("fma.rn.f32x2 %0,%1,%2,%3;" : "=l"(d) : "l"(a), "l"(b), "l"(c)); return d;
}

__global__ void __launch_bounds__(128)
qconv_kernel(const float* __restrict__ img,
             const float* __restrict__ wts,
             float* __restrict__ out,
             int npair)
{
    int tid = blockIdx.x * blockDim.x + threadIdx.x;
    if (tid >= npair) return;

    int b    = tid / 98;            // image
    int rem2 = tid - b * 98;        // j*7 + k2
    int j    = rem2 / 7;
    int k2   = rem2 - j * 7;        // pair of patches at cols 2*k2, 2*k2+1

    // 8 pixels for both patches: two float4 rows (16B aligned).
    const float4* rp = reinterpret_cast<const float4*>(
        img + (size_t)b * 784 + (size_t)(2 * j) * 28 + (size_t)(4 * k2));
    float4 q0 = rp[0];   // row 2j  : A.x0 A.x1 B.x0 B.x1
    float4 q1 = rp[7];   // row 2j+1: A.x2 A.x3 B.x2 B.x3

    u64 x0 = pk2(q0.x, q0.z);
    u64 x1 = pk2(q0.y, q0.w);
    u64 x2 = pk2(q1.x, q1.z);
    u64 x3 = pk2(q1.y, q1.w);

    const u64 HR2 = pk2(0.3925f, 0.3925f);   // 0.785/2
    u64 h0 = mul2(x0, HR2), h1 = mul2(x1, HR2);
    u64 h2 = mul2(x2, HR2), h3 = mul2(x3, HR2);
    u64 p01 = mul2(h0, x1), p02 = mul2(h0, x2), p03 = mul2(h0, x3);
    u64 p12 = mul2(h1, x2), p13 = mul2(h1, x3), p23 = mul2(h2, x3);

    // single-qubit phase bases
    u64 a01 = add2(h0, h1), b01 = sub2(h0, h1);
    u64 a23 = add2(h2, h3), b23 = sub2(h2, h3);
    u64 SA = add2(a01, a23), SB = sub2(a01, a23);
    u64 SC = add2(b01, a23), SD = sub2(b01, a23);
    u64 SE = add2(a01, b23), SF = sub2(a01, b23);
    u64 SG = add2(b01, b23), SH = sub2(b01, b23);

    // pair phase bases
    u64 m = add2(p12, p13), n = sub2(p12, p13);
    u64 t_pp = sub2(p01, m), t_mm = add2(p01, m);
    u64 t_pm = sub2(p01, n), t_mp = add2(p01, n);
    u64 u = add2(p02, p03), v = sub2(p02, p03);
    u64 q_pp = sub2(u, p23), q_mm = add2(u, p23);
    u64 q_pm = add2(v, p23), q_mp = sub2(v, p23);

    u64 P111  = add2(t_pp, q_pp);
    u64 P110  = add2(t_pm, q_pm);
    u64 P101  = sub2(t_mp, q_mp);
    u64 P100  = sub2(t_mm, q_mm);
    u64 P011  = sub2(q_pp, t_pp);
    u64 P010  = sub2(q_pm, t_pm);
    u64 Pn001 = add2(t_mp, q_mp);
    u64 Pn000 = add2(t_mm, q_mm);

    const u64 Z2 = pk2(0.0f, 0.0f);
    u64 psi[16];
    psi[0]  = sub2(Z2, add2(SA, Pn000));
    psi[1]  = sub2(Z2, add2(SE, Pn001));
    psi[2]  = sub2(P010, SF);
    psi[3]  = sub2(P011, SB);
    psi[4]  = sub2(P100, SC);
    psi[5]  = sub2(P101, SG);
    psi[6]  = sub2(P110, SH);
    psi[7]  = sub2(P111, SD);
    psi[8]  = add2(SD, P111);
    psi[9]  = add2(SH, P110);
    psi[10] = add2(SG, P101);
    psi[11] = add2(SC, P100);
    psi[12] = add2(SB, P011);
    psi[13] = add2(SF, P010);
    psi[14] = sub2(SE, Pn001);
    psi[15] = sub2(SA, Pn000);

    // amplitudes (unscaled): per-lane sincos, repacked
    u64 AR[16], AI[16];
#pragma unroll
    for (int s = 0; s < 16; ++s) {
        float pa, pb, sa, ca, sb, cb;
        unpk(psi[s], pa, pb);
        __sincosf(pa, &sa, &ca);
        __sincosf(pb, &sb, &cb);
        AR[s] = pk2(ca, cb);
        AI[s] = pk2(sa, sb);
    }

    // RX(w_q) butterflies (same angles for both lanes)
#pragma unroll
    for (int q = 0; q < 4; ++q) {
        float sw, cw;
        __sincosf(__ldg(wts + q) * 0.5f, &sw, &cw);
        u64 cw2 = pk2(cw, cw), sw2 = pk2(sw, sw);
        int bit = 1 << (3 - q);
#pragma unroll
        for (int s = 0; s < 16; ++s) {
            if (s & bit) continue;
            int t = s | bit;
            u64 a0r = AR[s], a0i = AI[s];
            u64 a1r = AR[t], a1i = AI[t];
            AR[s] = fma2(cw2, a0r, mul2(sw2, a1i));
            AI[s] = sub2(mul2(cw2, a0i), mul2(sw2, a1r));
            AR[t] = fma2(cw2, a1r, mul2(sw2, a0i));
            AI[t] = sub2(mul2(cw2, a1i), mul2(sw2, a0r));
        }
    }

    // probabilities
    u64 PZ[16];
#pragma unroll
    for (int s = 0; s < 16; ++s)
        PZ[s] = fma2(AI[s], AI[s], mul2(AR[s], AR[s]));

    // Walsh coefficients at masks 7, 12, 14, 15 (CNOT ring folded in)
    u64 d[8], sm[8];
#pragma unroll
    for (int i = 0; i < 8; ++i) {
        d[i]  = sub2(PZ[2 * i], PZ[2 * i + 1]);
        sm[i] = add2(PZ[2 * i], PZ[2 * i + 1]);
    }
    u64 dd[4], ss[4], sd[4];
#pragma unroll
    for (int i = 0; i < 4; ++i) {
        dd[i] = sub2(d[2 * i],  d[2 * i + 1]);
        ss[i] = add2(sm[2 * i], sm[2 * i + 1]);
        sd[i] = sub2(sm[2 * i], sm[2 * i + 1]);
    }
    u64 ddd0 = sub2(dd[0], dd[1]), ddd1 = sub2(dd[2], dd[3]);
    u64 ssd0 = sub2(ss[0], ss[1]), ssd1 = sub2(ss[2], ss[3]);
    u64 sdd0 = sub2(sd[0], sd[1]), sdd1 = sub2(sd[2], sd[3]);

    const u64 SC16 = pk2(0.0625f, 0.0625f);
    u64 ez0 = mul2(add2(ddd0, ddd1), SC16);   // mask 7  -> Z0
    u64 ez1 = mul2(sub2(ssd0, ssd1), SC16);   // mask 12 -> Z1
    u64 ez2 = mul2(sub2(sdd0, sdd1), SC16);   // mask 14 -> Z2
    u64 ez3 = mul2(sub2(ddd0, ddd1), SC16);   // mask 15 -> Z3

    // output (B,4,14,14), channels [Z3,Z2,Z1,Z0]; lane pair = adjacent k -> STG.64
    float* o = out + (size_t)b * 784 + (size_t)j * 14 + (size_t)(2 * k2);
    *reinterpret_cast<u64*>(o)       = ez3;
    *reinterpret_cast<u64*>(o + 196) = ez2;
    *reinterpret_cast<u64*>(o + 392) = ez1;
    *reinterpret_cast<u64*>(o + 588) = ez0;
}

extern "C" void kernel_launch(void* const* d_in, const int* in_sizes, int n_in,
                              void* d_out, int out_size) {
    const float* img = (const float*)d_in[0];
    const float* wts = (const float*)d_in[1];
    float* out = (float*)d_out;

    int B = in_sizes[0] / 784;
    int npair = B * 98;             // 14 * 7 patch-pairs per image

    int threads = 128;
    int blocks = (npair + threads - 1) / threads;
    qconv_kernel<<<blocks, threads>>>(img, wts, out, npair);
}